// round 1
// baseline (speedup 1.0000x reference)
#include <cuda_runtime.h>

// Problem constants
#define NB   16          // batch
#define CHN  512         // channels
#define NSP  1024        // spatial tokens (32*32)
#define GRP  8
#define CPG  (CHN / GRP) // 64

// Scratch (static device globals — allocation-rule safe)
__device__ float g_h[(size_t)NB * CHN * NSP];            // 32 MB  groupnorm output
__device__ float g_qkv[(size_t)NB * 3 * CHN * NSP];      // 96 MB  q|k|v per batch
__device__ float g_attn[(size_t)NB * NSP * NSP];         // 64 MB  attention scores
__device__ float g_out[(size_t)NB * CHN * NSP];          // 32 MB  attn @ v

// ---------------------------------------------------------------------------
// GroupNorm: one block per (batch, group). 64 ch * 1024 spatial = 65536 elems.
// ---------------------------------------------------------------------------
__global__ void groupnorm_kernel(const float* __restrict__ x,
                                 const float* __restrict__ w,
                                 const float* __restrict__ b,
                                 float* __restrict__ h) {
    const int bg    = blockIdx.x;
    const int batch = bg >> 3;
    const int g     = bg & 7;
    const size_t base = ((size_t)batch * CHN + (size_t)g * CPG) * NSP;
    const float* xp = x + base;
    float* hp = h + base;
    const int n = CPG * NSP;  // 65536

    float s = 0.f, ss = 0.f;
    for (int i = threadIdx.x * 4; i < n; i += blockDim.x * 4) {
        float4 v = *(const float4*)&xp[i];
        s  += v.x + v.y + v.z + v.w;
        ss += v.x * v.x + v.y * v.y + v.z * v.z + v.w * v.w;
    }
    // block reduce (256 threads)
    __shared__ float sa[8], sb[8];
    for (int o = 16; o > 0; o >>= 1) {
        s  += __shfl_xor_sync(0xffffffffu, s, o);
        ss += __shfl_xor_sync(0xffffffffu, ss, o);
    }
    int wid = threadIdx.x >> 5;
    if ((threadIdx.x & 31) == 0) { sa[wid] = s; sb[wid] = ss; }
    __syncthreads();
    s = 0.f; ss = 0.f;
#pragma unroll
    for (int i = 0; i < 8; i++) { s += sa[i]; ss += sb[i]; }

    const float inv_n = 1.f / (float)n;
    const float mean  = s * inv_n;
    const float var   = ss * inv_n - mean * mean;
    const float rstd  = rsqrtf(var + 1e-5f);

    for (int i = threadIdx.x * 4; i < n; i += blockDim.x * 4) {
        float4 v = *(const float4*)&xp[i];
        int c = g * CPG + (i >> 10);  // i / NSP (NSP=1024; 4 elems same row)
        float sc = w[c] * rstd;
        float bi = b[c] - mean * sc;
        v.x = v.x * sc + bi; v.y = v.y * sc + bi;
        v.z = v.z * sc + bi; v.w = v.w * sc + bi;
        *(float4*)&hp[i] = v;
    }
}

// ---------------------------------------------------------------------------
// Generic tiled fp32 GEMM: C[m,n] = sum_k opA(A)[m,k] * opB(B)[k,n]
//   TA=false: A is [M,K] row-major (lda=K).  TA=true: A is [K,M] (lda=M).
//   TB=false: B is [K,N] row-major (ldb=N).  TB=true: B is [N,K] (ldb=K).
// EPI: 0 plain | 1 +bias[m] | 2 *alpha | 3 +bias[m]+resid (residual add)
// C is always [M,N] row-major, ldc = N. blockIdx.z = batch (strides in elems).
// M % 64 == 0, N % 64 == 0, K % 16 == 0 assumed (true for all calls).
// ---------------------------------------------------------------------------
#define BM 64
#define BN 64
#define BK 16

template <bool TA, bool TB, int EPI>
__global__ void gemm_kernel(const float* __restrict__ Ag,
                            const float* __restrict__ Bg,
                            float* __restrict__ Cg,
                            int M, int N, int K, int lda, int ldb,
                            long long sA, long long sB, long long sC,
                            const float* __restrict__ bias,
                            const float* __restrict__ resid, long long sR,
                            float alpha) {
    const float* A = Ag + (size_t)blockIdx.z * sA;
    const float* B = Bg + (size_t)blockIdx.z * sB;
    float* C       = Cg + (size_t)blockIdx.z * sC;

    __shared__ __align__(16) float As[BK][BM];
    __shared__ __align__(16) float Bs[BK][BN];

    const int tid = threadIdx.y * 16 + threadIdx.x;
    const int m0 = blockIdx.y * BM;
    const int n0 = blockIdx.x * BN;

    float acc[4][4] = {};

    for (int k0 = 0; k0 < K; k0 += BK) {
        // ---- load A tile ----
        if (!TA) {
            int row = tid >> 2;          // 0..63 (m within tile)
            int kk  = (tid & 3) << 2;    // 0,4,8,12
            float4 a = *(const float4*)&A[(size_t)(m0 + row) * lda + k0 + kk];
            As[kk + 0][row] = a.x; As[kk + 1][row] = a.y;
            As[kk + 2][row] = a.z; As[kk + 3][row] = a.w;
        } else {
            int kk = tid >> 4;           // 0..15
            int mm = (tid & 15) << 2;    // 0..60
            *(float4*)&As[kk][mm] =
                *(const float4*)&A[(size_t)(k0 + kk) * lda + m0 + mm];
        }
        // ---- load B tile ----
        if (!TB) {
            int kk = tid >> 4;
            int nn = (tid & 15) << 2;
            *(float4*)&Bs[kk][nn] =
                *(const float4*)&B[(size_t)(k0 + kk) * ldb + n0 + nn];
        } else {
            int row = tid >> 2;          // n within tile
            int kk  = (tid & 3) << 2;
            float4 bv = *(const float4*)&B[(size_t)(n0 + row) * ldb + k0 + kk];
            Bs[kk + 0][row] = bv.x; Bs[kk + 1][row] = bv.y;
            Bs[kk + 2][row] = bv.z; Bs[kk + 3][row] = bv.w;
        }
        __syncthreads();

#pragma unroll
        for (int kk = 0; kk < BK; kk++) {
            float4 a = *(const float4*)&As[kk][threadIdx.y << 2];
            float4 bq = *(const float4*)&Bs[kk][threadIdx.x << 2];
            float av[4] = {a.x, a.y, a.z, a.w};
            float bv[4] = {bq.x, bq.y, bq.z, bq.w};
#pragma unroll
            for (int i = 0; i < 4; i++)
#pragma unroll
                for (int j = 0; j < 4; j++)
                    acc[i][j] += av[i] * bv[j];
        }
        __syncthreads();
    }

    // ---- epilogue ----
    const int mbase = m0 + (threadIdx.y << 2);
    const int nbase = n0 + (threadIdx.x << 2);
#pragma unroll
    for (int i = 0; i < 4; i++) {
        int m = mbase + i;
        float4 out;
        out.x = acc[i][0]; out.y = acc[i][1];
        out.z = acc[i][2]; out.w = acc[i][3];
        if (EPI == 2) {
            out.x *= alpha; out.y *= alpha; out.z *= alpha; out.w *= alpha;
        }
        if (EPI == 1 || EPI == 3) {
            float bb = bias[m];
            out.x += bb; out.y += bb; out.z += bb; out.w += bb;
        }
        if (EPI == 3) {
            const float* rp =
                resid + (size_t)blockIdx.z * sR + (size_t)m * N + nbase;
            float4 rv = *(const float4*)rp;
            out.x += rv.x; out.y += rv.y; out.z += rv.z; out.w += rv.w;
        }
        *(float4*)&C[(size_t)m * N + nbase] = out;
    }
}

// ---------------------------------------------------------------------------
// Row softmax: one block per row of attn (B*N rows of length N=1024).
// ---------------------------------------------------------------------------
__global__ void softmax_kernel(float* __restrict__ attn) {
    __shared__ float red[8];
    float* row = attn + (size_t)blockIdx.x * NSP;
    float4 v = ((float4*)row)[threadIdx.x];

    float m = fmaxf(fmaxf(v.x, v.y), fmaxf(v.z, v.w));
    for (int o = 16; o > 0; o >>= 1)
        m = fmaxf(m, __shfl_xor_sync(0xffffffffu, m, o));
    int w = threadIdx.x >> 5;
    if ((threadIdx.x & 31) == 0) red[w] = m;
    __syncthreads();
    m = red[0];
#pragma unroll
    for (int i = 1; i < 8; i++) m = fmaxf(m, red[i]);

    v.x = __expf(v.x - m); v.y = __expf(v.y - m);
    v.z = __expf(v.z - m); v.w = __expf(v.w - m);
    float s = v.x + v.y + v.z + v.w;
    for (int o = 16; o > 0; o >>= 1)
        s += __shfl_xor_sync(0xffffffffu, s, o);
    __syncthreads();
    if ((threadIdx.x & 31) == 0) red[w] = s;
    __syncthreads();
    s = red[0] + red[1] + red[2] + red[3] + red[4] + red[5] + red[6] + red[7];
    float inv = 1.0f / s;
    v.x *= inv; v.y *= inv; v.z *= inv; v.w *= inv;
    ((float4*)row)[threadIdx.x] = v;
}

// ---------------------------------------------------------------------------
// Launch
// ---------------------------------------------------------------------------
extern "C" void kernel_launch(void* const* d_in, const int* in_sizes, int n_in,
                              void* d_out, int out_size) {
    const float* x     = (const float*)d_in[0];
    const float* nw    = (const float*)d_in[1];
    const float* nbias = (const float*)d_in[2];
    const float* qkvw  = (const float*)d_in[3];
    const float* qkvb  = (const float*)d_in[4];
    const float* pw    = (const float*)d_in[5];
    const float* pb    = (const float*)d_in[6];
    float* out = (float*)d_out;

    float *ph, *pqkv, *pattn, *pout;
    cudaGetSymbolAddress((void**)&ph,    g_h);
    cudaGetSymbolAddress((void**)&pqkv,  g_qkv);
    cudaGetSymbolAddress((void**)&pattn, g_attn);
    cudaGetSymbolAddress((void**)&pout,  g_out);

    const long long CN  = (long long)CHN * NSP;       // 524288
    const long long C3N = 3LL * CHN * NSP;            // per-batch qkv stride
    const long long NN  = (long long)NSP * NSP;       // per-batch attn stride
    const float scale = 0.044194173824159216f;        // 512^-0.5

    dim3 th(16, 16);

    // 1) GroupNorm  -> g_h  [B, C, N]
    groupnorm_kernel<<<NB * GRP, 256>>>(x, nw, nbias, ph);

    // 2) QKV: qkv[b] = qkv_w[3C,C] @ h[b][C,N] + qkv_b   (NN, bias)
    gemm_kernel<false, false, 1><<<dim3(NSP / BN, (3 * CHN) / BM, NB), th>>>(
        qkvw, ph, pqkv, 3 * CHN, NSP, CHN, CHN, NSP,
        0LL, CN, C3N, qkvb, nullptr, 0LL, 1.f);

    // 3) Scores: attn[b,i,j] = scale * sum_c q[b,c,i] k[b,c,j]  (TN, scale)
    gemm_kernel<true, false, 2><<<dim3(NSP / BN, NSP / BM, NB), th>>>(
        pqkv, pqkv + CN, pattn, NSP, NSP, CHN, NSP, NSP,
        C3N, C3N, NN, nullptr, nullptr, 0LL, scale);

    // 4) Softmax over j
    softmax_kernel<<<NB * NSP, 256>>>(pattn);

    // 5) out[b,c,i] = sum_j v[b,c,j] attn[b,i,j]   (NT)
    gemm_kernel<false, true, 0><<<dim3(NSP / BN, CHN / BM, NB), th>>>(
        pqkv + 2 * CN, pattn, pout, CHN, NSP, NSP, NSP, NSP,
        C3N, NN, CN, nullptr, nullptr, 0LL, 1.f);

    // 6) proj + bias + residual -> d_out   (NN, bias+resid)
    gemm_kernel<false, false, 3><<<dim3(NSP / BN, CHN / BM, NB), th>>>(
        pw, pout, out, CHN, NSP, CHN, CHN, NSP,
        0LL, CN, CN, pb, x, CN, 1.f);
}

// round 2
// speedup vs baseline: 1.0004x; 1.0004x over previous
#include <cuda_runtime.h>

// Problem constants
#define NB   16          // batch
#define CHN  512         // channels
#define NSP  1024        // spatial tokens (32*32)
#define GRP  8
#define CPG  (CHN / GRP) // 64

// Scratch (static device globals — allocation-rule safe)
__device__ float g_h[(size_t)NB * CHN * NSP];            // 32 MB  groupnorm output
__device__ float g_qkv[(size_t)NB * 3 * CHN * NSP];      // 96 MB  q|k|v per batch
__device__ float g_attn[(size_t)NB * NSP * NSP];         // 64 MB  attention scores
__device__ float g_out[(size_t)NB * CHN * NSP];          // 32 MB  attn @ v

// ---------------------------------------------------------------------------
// GroupNorm: one block per (batch, group). 64 ch * 1024 spatial = 65536 elems.
// ---------------------------------------------------------------------------
__global__ void groupnorm_kernel(const float* __restrict__ x,
                                 const float* __restrict__ w,
                                 const float* __restrict__ b,
                                 float* __restrict__ h) {
    const int bg    = blockIdx.x;
    const int batch = bg >> 3;
    const int g     = bg & 7;
    const size_t base = ((size_t)batch * CHN + (size_t)g * CPG) * NSP;
    const float* xp = x + base;
    float* hp = h + base;
    const int n = CPG * NSP;  // 65536

    float s = 0.f, ss = 0.f;
    for (int i = threadIdx.x * 4; i < n; i += blockDim.x * 4) {
        float4 v = *(const float4*)&xp[i];
        s  += v.x + v.y + v.z + v.w;
        ss += v.x * v.x + v.y * v.y + v.z * v.z + v.w * v.w;
    }
    // block reduce (256 threads)
    __shared__ float sa[8], sb[8];
    for (int o = 16; o > 0; o >>= 1) {
        s  += __shfl_xor_sync(0xffffffffu, s, o);
        ss += __shfl_xor_sync(0xffffffffu, ss, o);
    }
    int wid = threadIdx.x >> 5;
    if ((threadIdx.x & 31) == 0) { sa[wid] = s; sb[wid] = ss; }
    __syncthreads();
    s = 0.f; ss = 0.f;
#pragma unroll
    for (int i = 0; i < 8; i++) { s += sa[i]; ss += sb[i]; }

    const float inv_n = 1.f / (float)n;
    const float mean  = s * inv_n;
    const float var   = ss * inv_n - mean * mean;
    const float rstd  = rsqrtf(var + 1e-5f);

    for (int i = threadIdx.x * 4; i < n; i += blockDim.x * 4) {
        float4 v = *(const float4*)&xp[i];
        int c = g * CPG + (i >> 10);  // i / NSP (NSP=1024; 4 elems same row)
        float sc = w[c] * rstd;
        float bi = b[c] - mean * sc;
        v.x = v.x * sc + bi; v.y = v.y * sc + bi;
        v.z = v.z * sc + bi; v.w = v.w * sc + bi;
        *(float4*)&hp[i] = v;
    }
}

// ---------------------------------------------------------------------------
// Generic tiled fp32 GEMM: C[m,n] = sum_k opA(A)[m,k] * opB(B)[k,n]
//   TA=false: A is [M,K] row-major (lda=K).  TA=true: A is [K,M] (lda=M).
//   TB=false: B is [K,N] row-major (ldb=N).  TB=true: B is [N,K] (ldb=K).
// EPI: 0 plain | 1 +bias[m] | 2 *alpha | 3 +bias[m]+resid (residual add)
// C is always [M,N] row-major, ldc = N. blockIdx.z = batch (strides in elems).
// M % 64 == 0, N % 64 == 0, K % 16 == 0 assumed (true for all calls).
// ---------------------------------------------------------------------------
#define BM 64
#define BN 64
#define BK 16

template <bool TA, bool TB, int EPI>
__global__ void gemm_kernel(const float* __restrict__ Ag,
                            const float* __restrict__ Bg,
                            float* __restrict__ Cg,
                            int M, int N, int K, int lda, int ldb,
                            long long sA, long long sB, long long sC,
                            const float* __restrict__ bias,
                            const float* __restrict__ resid, long long sR,
                            float alpha) {
    const float* A = Ag + (size_t)blockIdx.z * sA;
    const float* B = Bg + (size_t)blockIdx.z * sB;
    float* C       = Cg + (size_t)blockIdx.z * sC;

    __shared__ __align__(16) float As[BK][BM];
    __shared__ __align__(16) float Bs[BK][BN];

    const int tid = threadIdx.y * 16 + threadIdx.x;
    const int m0 = blockIdx.y * BM;
    const int n0 = blockIdx.x * BN;

    float acc[4][4] = {};

    for (int k0 = 0; k0 < K; k0 += BK) {
        // ---- load A tile ----
        if (!TA) {
            int row = tid >> 2;          // 0..63 (m within tile)
            int kk  = (tid & 3) << 2;    // 0,4,8,12
            float4 a = *(const float4*)&A[(size_t)(m0 + row) * lda + k0 + kk];
            As[kk + 0][row] = a.x; As[kk + 1][row] = a.y;
            As[kk + 2][row] = a.z; As[kk + 3][row] = a.w;
        } else {
            int kk = tid >> 4;           // 0..15
            int mm = (tid & 15) << 2;    // 0..60
            *(float4*)&As[kk][mm] =
                *(const float4*)&A[(size_t)(k0 + kk) * lda + m0 + mm];
        }
        // ---- load B tile ----
        if (!TB) {
            int kk = tid >> 4;
            int nn = (tid & 15) << 2;
            *(float4*)&Bs[kk][nn] =
                *(const float4*)&B[(size_t)(k0 + kk) * ldb + n0 + nn];
        } else {
            int row = tid >> 2;          // n within tile
            int kk  = (tid & 3) << 2;
            float4 bv = *(const float4*)&B[(size_t)(n0 + row) * ldb + k0 + kk];
            Bs[kk + 0][row] = bv.x; Bs[kk + 1][row] = bv.y;
            Bs[kk + 2][row] = bv.z; Bs[kk + 3][row] = bv.w;
        }
        __syncthreads();

#pragma unroll
        for (int kk = 0; kk < BK; kk++) {
            float4 a = *(const float4*)&As[kk][threadIdx.y << 2];
            float4 bq = *(const float4*)&Bs[kk][threadIdx.x << 2];
            float av[4] = {a.x, a.y, a.z, a.w};
            float bv[4] = {bq.x, bq.y, bq.z, bq.w};
#pragma unroll
            for (int i = 0; i < 4; i++)
#pragma unroll
                for (int j = 0; j < 4; j++)
                    acc[i][j] += av[i] * bv[j];
        }
        __syncthreads();
    }

    // ---- epilogue ----
    const int mbase = m0 + (threadIdx.y << 2);
    const int nbase = n0 + (threadIdx.x << 2);
#pragma unroll
    for (int i = 0; i < 4; i++) {
        int m = mbase + i;
        float4 out;
        out.x = acc[i][0]; out.y = acc[i][1];
        out.z = acc[i][2]; out.w = acc[i][3];
        if (EPI == 2) {
            out.x *= alpha; out.y *= alpha; out.z *= alpha; out.w *= alpha;
        }
        if (EPI == 1 || EPI == 3) {
            float bb = bias[m];
            out.x += bb; out.y += bb; out.z += bb; out.w += bb;
        }
        if (EPI == 3) {
            const float* rp =
                resid + (size_t)blockIdx.z * sR + (size_t)m * N + nbase;
            float4 rv = *(const float4*)rp;
            out.x += rv.x; out.y += rv.y; out.z += rv.z; out.w += rv.w;
        }
        *(float4*)&C[(size_t)m * N + nbase] = out;
    }
}

// ---------------------------------------------------------------------------
// Row softmax: one block per row of attn (B*N rows of length N=1024).
// ---------------------------------------------------------------------------
__global__ void softmax_kernel(float* __restrict__ attn) {
    __shared__ float red[8];
    float* row = attn + (size_t)blockIdx.x * NSP;
    float4 v = ((float4*)row)[threadIdx.x];

    float m = fmaxf(fmaxf(v.x, v.y), fmaxf(v.z, v.w));
    for (int o = 16; o > 0; o >>= 1)
        m = fmaxf(m, __shfl_xor_sync(0xffffffffu, m, o));
    int w = threadIdx.x >> 5;
    if ((threadIdx.x & 31) == 0) red[w] = m;
    __syncthreads();
    m = red[0];
#pragma unroll
    for (int i = 1; i < 8; i++) m = fmaxf(m, red[i]);

    v.x = __expf(v.x - m); v.y = __expf(v.y - m);
    v.z = __expf(v.z - m); v.w = __expf(v.w - m);
    float s = v.x + v.y + v.z + v.w;
    for (int o = 16; o > 0; o >>= 1)
        s += __shfl_xor_sync(0xffffffffu, s, o);
    __syncthreads();
    if ((threadIdx.x & 31) == 0) red[w] = s;
    __syncthreads();
    s = red[0] + red[1] + red[2] + red[3] + red[4] + red[5] + red[6] + red[7];
    float inv = 1.0f / s;
    v.x *= inv; v.y *= inv; v.z *= inv; v.w *= inv;
    ((float4*)row)[threadIdx.x] = v;
}

// ---------------------------------------------------------------------------
// Launch
// ---------------------------------------------------------------------------
extern "C" void kernel_launch(void* const* d_in, const int* in_sizes, int n_in,
                              void* d_out, int out_size) {
    const float* x     = (const float*)d_in[0];
    const float* nw    = (const float*)d_in[1];
    const float* nbias = (const float*)d_in[2];
    const float* qkvw  = (const float*)d_in[3];
    const float* qkvb  = (const float*)d_in[4];
    const float* pw    = (const float*)d_in[5];
    const float* pb    = (const float*)d_in[6];
    float* out = (float*)d_out;

    float *ph, *pqkv, *pattn, *pout;
    cudaGetSymbolAddress((void**)&ph,    g_h);
    cudaGetSymbolAddress((void**)&pqkv,  g_qkv);
    cudaGetSymbolAddress((void**)&pattn, g_attn);
    cudaGetSymbolAddress((void**)&pout,  g_out);

    const long long CN  = (long long)CHN * NSP;       // 524288
    const long long C3N = 3LL * CHN * NSP;            // per-batch qkv stride
    const long long NN  = (long long)NSP * NSP;       // per-batch attn stride
    const float scale = 0.044194173824159216f;        // 512^-0.5

    dim3 th(16, 16);

    // 1) GroupNorm  -> g_h  [B, C, N]
    groupnorm_kernel<<<NB * GRP, 256>>>(x, nw, nbias, ph);

    // 2) QKV: qkv[b] = qkv_w[3C,C] @ h[b][C,N] + qkv_b   (NN, bias)
    gemm_kernel<false, false, 1><<<dim3(NSP / BN, (3 * CHN) / BM, NB), th>>>(
        qkvw, ph, pqkv, 3 * CHN, NSP, CHN, CHN, NSP,
        0LL, CN, C3N, qkvb, nullptr, 0LL, 1.f);

    // 3) Scores: attn[b,i,j] = scale * sum_c q[b,c,i] k[b,c,j]  (TN, scale)
    gemm_kernel<true, false, 2><<<dim3(NSP / BN, NSP / BM, NB), th>>>(
        pqkv, pqkv + CN, pattn, NSP, NSP, CHN, NSP, NSP,
        C3N, C3N, NN, nullptr, nullptr, 0LL, scale);

    // 4) Softmax over j
    softmax_kernel<<<NB * NSP, 256>>>(pattn);

    // 5) out[b,c,i] = sum_j v[b,c,j] attn[b,i,j]   (NT)
    gemm_kernel<false, true, 0><<<dim3(NSP / BN, CHN / BM, NB), th>>>(
        pqkv + 2 * CN, pattn, pout, CHN, NSP, NSP, NSP, NSP,
        C3N, NN, CN, nullptr, nullptr, 0LL, 1.f);

    // 6) proj + bias + residual -> d_out   (NN, bias+resid)
    gemm_kernel<false, false, 3><<<dim3(NSP / BN, CHN / BM, NB), th>>>(
        pw, pout, out, CHN, NSP, CHN, CHN, NSP,
        0LL, CN, CN, pb, x, CN, 1.f);
}

// round 4
// speedup vs baseline: 2.3645x; 2.3636x over previous
#include <cuda_runtime.h>
#include <cuda_bf16.h>

#define NB   16
#define CHN  512
#define NSP  1024

// Scratch (__device__ globals — allocation-rule safe)
__device__ __nv_bfloat16 g_hT_h[(size_t)NB * NSP * CHN];
__device__ __nv_bfloat16 g_hT_l[(size_t)NB * NSP * CHN];
__device__ __nv_bfloat16 g_qkT_h[(size_t)NB * NSP * 2 * CHN];
__device__ __nv_bfloat16 g_qkT_l[(size_t)NB * NSP * 2 * CHN];
__device__ __nv_bfloat16 g_v_h[(size_t)NB * CHN * NSP];
__device__ __nv_bfloat16 g_v_l[(size_t)NB * CHN * NSP];
__device__ float         g_attn[(size_t)NB * NSP * NSP];
__device__ __nv_bfloat16 g_attn_h[(size_t)NB * NSP * NSP];
__device__ __nv_bfloat16 g_attn_l[(size_t)NB * NSP * NSP];
__device__ __nv_bfloat16 g_oT_h[(size_t)NB * NSP * CHN];
__device__ __nv_bfloat16 g_oT_l[(size_t)NB * NSP * CHN];
__device__ __nv_bfloat16 g_wqkv_h[3 * CHN * CHN];
__device__ __nv_bfloat16 g_wqkv_l[3 * CHN * CHN];
__device__ __nv_bfloat16 g_wp_h[CHN * CHN];
__device__ __nv_bfloat16 g_wp_l[CHN * CHN];

// ---------------- helpers ----------------
__device__ __forceinline__ unsigned smem_u32(const void* p) {
    unsigned a;
    asm("{ .reg .u64 t; cvta.to.shared.u64 t, %1; cvt.u32.u64 %0, t; }"
        : "=r"(a) : "l"(p));
    return a;
}
__device__ __forceinline__ void bsplit(float x, __nv_bfloat16& h, __nv_bfloat16& l) {
    h = __float2bfloat16_rn(x);
    l = __float2bfloat16_rn(x - __bfloat162float(h));
}
__device__ __forceinline__ void ldsm4(unsigned r[4], unsigned addr) {
    asm volatile("ldmatrix.sync.aligned.m8n8.x4.shared.b16 {%0,%1,%2,%3}, [%4];"
                 : "=r"(r[0]), "=r"(r[1]), "=r"(r[2]), "=r"(r[3]) : "r"(addr));
}
__device__ __forceinline__ void ldsm2(unsigned r[2], unsigned addr) {
    asm volatile("ldmatrix.sync.aligned.m8n8.x2.shared.b16 {%0,%1}, [%2];"
                 : "=r"(r[0]), "=r"(r[1]) : "r"(addr));
}
__device__ __forceinline__ void mma16816(float c[4], const unsigned a[4], const unsigned b[2]) {
    asm volatile(
        "mma.sync.aligned.m16n8k16.row.col.f32.bf16.bf16.f32 "
        "{%0,%1,%2,%3}, {%4,%5,%6,%7}, {%8,%9}, {%0,%1,%2,%3};"
        : "+f"(c[0]), "+f"(c[1]), "+f"(c[2]), "+f"(c[3])
        : "r"(a[0]), "r"(a[1]), "r"(a[2]), "r"(a[3]), "r"(b[0]), "r"(b[1]));
}

// ---------------------------------------------------------------------------
// GEMM D[m,n] = sum_k A[m,k]*B[n,k] (both K-major), bf16 hi/lo split, fp32 acc.
// Block tile 128x128, KC=32. 8 warps (2x4), warp tile 64x32. mma.m16n8k16.
// EPI: 0 QK(+bias[n], split out) | 1 V(+bias[m], split out) | 2 SCORE(*alpha, f32)
//      3 AV(split out) | 4 PROJ(+bias[m]+resid, f32)
// ---------------------------------------------------------------------------
#define MT 128
#define NT 128
#define KC 32
#define PITCH 80                 // bytes per smem row (40 halves; conflict-free)
#define TILE_B (128 * PITCH)     // 10240
#define OFF_AH 0
#define OFF_AL TILE_B
#define OFF_BH (2 * TILE_B)
#define OFF_BL (3 * TILE_B)
#define STAGE  (4 * TILE_B)      // 40960
#define SMEM_BYTES (2 * STAGE)   // 81920

template <int EPI>
__global__ void __launch_bounds__(256) mma_gemm(
    const __nv_bfloat16* __restrict__ Ah, const __nv_bfloat16* __restrict__ Al,
    int lda, long long sA,
    const __nv_bfloat16* __restrict__ Bh, const __nv_bfloat16* __restrict__ Bl,
    int ldb, long long sB, int K,
    float* __restrict__ Cf, __nv_bfloat16* __restrict__ Ch, __nv_bfloat16* __restrict__ Cl,
    int ldc, long long sC,
    const float* __restrict__ bias,
    const float* __restrict__ resid, long long sR, float alpha) {
    extern __shared__ char smem[];
    const unsigned sb = smem_u32(smem);
    const int tid = threadIdx.x, lane = tid & 31, wid = tid >> 5;
    const int m0 = blockIdx.y * MT, n0 = blockIdx.x * NT, bz = blockIdx.z;
    const int wm0 = (wid >> 2) * 64, wn0 = (wid & 3) * 32;

    const __nv_bfloat16* Ab_h = Ah + (size_t)bz * sA + (size_t)m0 * lda;
    const __nv_bfloat16* Ab_l = Al + (size_t)bz * sA + (size_t)m0 * lda;
    const __nv_bfloat16* Bb_h = Bh + (size_t)bz * sB + (size_t)n0 * ldb;
    const __nv_bfloat16* Bb_l = Bl + (size_t)bz * sB + (size_t)n0 * ldb;

    // global<->smem fill mapping: thread t -> row t/2, 32B segment (t&1)
    const int grow = tid >> 1;
    const int gsegB = (tid & 1) * 32;

    // ldmatrix per-lane addresses
    const unsigned aLane = (unsigned)((wm0 + (lane & 15)) * PITCH + ((lane >> 4) & 1) * 16);
    const unsigned bLane = (unsigned)((wn0 + (lane & 7)) * PITCH + ((lane >> 3) & 1) * 16);

    uint4 pf[8];
    auto ldg = [&](int ko) {
        const char* p;
        p = (const char*)(Ab_h + (size_t)grow * lda + ko) + gsegB;
        pf[0] = *(const uint4*)p; pf[1] = *(const uint4*)(p + 16);
        p = (const char*)(Ab_l + (size_t)grow * lda + ko) + gsegB;
        pf[2] = *(const uint4*)p; pf[3] = *(const uint4*)(p + 16);
        p = (const char*)(Bb_h + (size_t)grow * ldb + ko) + gsegB;
        pf[4] = *(const uint4*)p; pf[5] = *(const uint4*)(p + 16);
        p = (const char*)(Bb_l + (size_t)grow * ldb + ko) + gsegB;
        pf[6] = *(const uint4*)p; pf[7] = *(const uint4*)(p + 16);
    };
    auto sts = [&](int stg) {
        char* d = smem + stg * STAGE + grow * PITCH + gsegB;
        *(uint4*)(d + OFF_AH) = pf[0]; *(uint4*)(d + OFF_AH + 16) = pf[1];
        *(uint4*)(d + OFF_AL) = pf[2]; *(uint4*)(d + OFF_AL + 16) = pf[3];
        *(uint4*)(d + OFF_BH) = pf[4]; *(uint4*)(d + OFF_BH + 16) = pf[5];
        *(uint4*)(d + OFF_BL) = pf[6]; *(uint4*)(d + OFF_BL + 16) = pf[7];
    };

    ldg(0); sts(0);
    __syncthreads();

    float acc[4][4][4] = {};
    const int nch = K / KC;

    for (int c = 0; c < nch; c++) {
        if (c + 1 < nch) ldg((c + 1) * KC);
        const unsigned sbuf = sb + (c & 1) * STAGE;
#pragma unroll
        for (int ks = 0; ks < 2; ks++) {
            unsigned ah[4][4], al[4][4], bh[4][2], bl[4][2];
#pragma unroll
            for (int am = 0; am < 4; am++) {
                unsigned ad = sbuf + aLane + am * (16 * PITCH) + ks * 32;
                ldsm4(ah[am], ad + OFF_AH);
                ldsm4(al[am], ad + OFF_AL);
            }
#pragma unroll
            for (int an = 0; an < 4; an++) {
                unsigned bd = sbuf + bLane + an * (8 * PITCH) + ks * 32;
                ldsm2(bh[an], bd + OFF_BH);
                ldsm2(bl[an], bd + OFF_BL);
            }
            // three independent sweeps: 16 independent accumulators each
#pragma unroll
            for (int am = 0; am < 4; am++)
#pragma unroll
                for (int an = 0; an < 4; an++)
                    mma16816(acc[am][an], ah[am], bh[an]);
#pragma unroll
            for (int am = 0; am < 4; am++)
#pragma unroll
                for (int an = 0; an < 4; an++)
                    mma16816(acc[am][an], ah[am], bl[an]);
#pragma unroll
            for (int am = 0; am < 4; am++)
#pragma unroll
                for (int an = 0; an < 4; an++)
                    mma16816(acc[am][an], al[am], bh[an]);
        }
        if (c + 1 < nch) sts((c + 1) & 1);
        __syncthreads();
    }

    // ---- epilogue ----
    const int r0 = m0 + wm0 + (lane >> 2);
    const int c0 = n0 + wn0 + (lane & 3) * 2;
#pragma unroll
    for (int am = 0; am < 4; am++) {
#pragma unroll
        for (int an = 0; an < 4; an++) {
            float f0 = acc[am][an][0], f1 = acc[am][an][1];
            float f2 = acc[am][an][2], f3 = acc[am][an][3];
            const int r = r0 + am * 16;
            const int cc = c0 + an * 8;
            if (EPI == 2) { f0 *= alpha; f1 *= alpha; f2 *= alpha; f3 *= alpha; }
            if (EPI == 0) {
                float b0 = bias[cc], b1 = bias[cc + 1];
                f0 += b0; f1 += b1; f2 += b0; f3 += b1;
            }
            if (EPI == 1 || EPI == 4) {
                float ba = bias[r], bb = bias[r + 8];
                f0 += ba; f1 += ba; f2 += bb; f3 += bb;
            }
            const size_t o0 = (size_t)bz * sC + (size_t)r * ldc + cc;
            const size_t o1 = o0 + (size_t)8 * ldc;
            if (EPI == 4) {
                const float* rp = resid + (size_t)bz * sR + (size_t)r * ldc + cc;
                float2 rv0 = *(const float2*)rp;
                float2 rv1 = *(const float2*)(rp + (size_t)8 * ldc);
                f0 += rv0.x; f1 += rv0.y; f2 += rv1.x; f3 += rv1.y;
            }
            if (EPI == 2 || EPI == 4) {
                *(float2*)(Cf + o0) = make_float2(f0, f1);
                *(float2*)(Cf + o1) = make_float2(f2, f3);
            } else {
                union { __nv_bfloat16 b[2]; unsigned u; } H0, L0, H1, L1;
                bsplit(f0, H0.b[0], L0.b[0]); bsplit(f1, H0.b[1], L0.b[1]);
                bsplit(f2, H1.b[0], L1.b[0]); bsplit(f3, H1.b[1], L1.b[1]);
                *(unsigned*)(Ch + o0) = H0.u; *(unsigned*)(Cl + o0) = L0.u;
                *(unsigned*)(Ch + o1) = H1.u; *(unsigned*)(Cl + o1) = L1.u;
            }
        }
    }
}

// ---------------------------------------------------------------------------
// GroupNorm -> transposed bf16 hi/lo output hT[B, N, C]
// ---------------------------------------------------------------------------
__global__ void __launch_bounds__(256) groupnorm_t(const float* __restrict__ x,
                                                   const float* __restrict__ gw,
                                                   const float* __restrict__ gb,
                                                   __nv_bfloat16* __restrict__ hh,
                                                   __nv_bfloat16* __restrict__ hl) {
    const int b = blockIdx.x >> 3, g = blockIdx.x & 7;
    const float* xp = x + ((size_t)b * CHN + (size_t)g * 64) * NSP;

    float s = 0.f, ss = 0.f;
    for (int i = threadIdx.x * 4; i < 64 * NSP; i += 1024) {
        float4 v = *(const float4*)(xp + i);
        s += v.x + v.y + v.z + v.w;
        ss += v.x * v.x + v.y * v.y + v.z * v.z + v.w * v.w;
    }
    __shared__ float sa[8], sb2[8];
    for (int o = 16; o > 0; o >>= 1) {
        s += __shfl_xor_sync(0xffffffffu, s, o);
        ss += __shfl_xor_sync(0xffffffffu, ss, o);
    }
    if ((threadIdx.x & 31) == 0) { sa[threadIdx.x >> 5] = s; sb2[threadIdx.x >> 5] = ss; }
    __syncthreads();
    s = 0.f; ss = 0.f;
#pragma unroll
    for (int i = 0; i < 8; i++) { s += sa[i]; ss += sb2[i]; }
    const float inv_n = 1.f / (64.f * (float)NSP);
    const float mean = s * inv_n;
    const float rstd = rsqrtf(ss * inv_n - mean * mean + 1e-5f);

    const int ci_w = threadIdx.x & 63;
    const int cg = g * 64 + ci_w;
    const float sc = gw[cg] * rstd;
    const float bi = gb[cg] - mean * sc;

    __shared__ float tile[64][65];
    const int ci_r = threadIdx.x >> 2;
    const int nj = (threadIdx.x & 3) * 16;
    const int nbase = (threadIdx.x >> 6) * 16;

    for (int tt = 0; tt < 16; tt++) {
        const int n0 = tt * 64;
        __syncthreads();
        const float* src = xp + (size_t)ci_r * NSP + n0 + nj;
#pragma unroll
        for (int q = 0; q < 4; q++) {
            float4 v = *(const float4*)(src + q * 4);
            tile[ci_r][nj + q*4 + 0] = v.x; tile[ci_r][nj + q*4 + 1] = v.y;
            tile[ci_r][nj + q*4 + 2] = v.z; tile[ci_r][nj + q*4 + 3] = v.w;
        }
        __syncthreads();
#pragma unroll
        for (int k = 0; k < 16; k++) {
            const int nl = nbase + k;
            float y = tile[ci_w][nl] * sc + bi;
            __nv_bfloat16 h, l;
            bsplit(y, h, l);
            const size_t o = ((size_t)b * NSP + n0 + nl) * CHN + cg;
            hh[o] = h; hl[o] = l;
        }
    }
}

// ---------------------------------------------------------------------------
// Softmax (fp32 in) -> bf16 hi/lo probs
// ---------------------------------------------------------------------------
__global__ void __launch_bounds__(256) softmax_split(const float* __restrict__ a,
                                                     __nv_bfloat16* __restrict__ oh,
                                                     __nv_bfloat16* __restrict__ ol) {
    __shared__ float red[8];
    const float* row = a + (size_t)blockIdx.x * NSP;
    float4 v = ((const float4*)row)[threadIdx.x];

    float m = fmaxf(fmaxf(v.x, v.y), fmaxf(v.z, v.w));
    for (int o = 16; o > 0; o >>= 1) m = fmaxf(m, __shfl_xor_sync(0xffffffffu, m, o));
    int w = threadIdx.x >> 5;
    if ((threadIdx.x & 31) == 0) red[w] = m;
    __syncthreads();
    m = red[0];
#pragma unroll
    for (int i = 1; i < 8; i++) m = fmaxf(m, red[i]);

    v.x = __expf(v.x - m); v.y = __expf(v.y - m);
    v.z = __expf(v.z - m); v.w = __expf(v.w - m);
    float su = v.x + v.y + v.z + v.w;
    for (int o = 16; o > 0; o >>= 1) su += __shfl_xor_sync(0xffffffffu, su, o);
    __syncthreads();
    if ((threadIdx.x & 31) == 0) red[w] = su;
    __syncthreads();
    su = red[0] + red[1] + red[2] + red[3] + red[4] + red[5] + red[6] + red[7];
    float inv = 1.0f / su;
    v.x *= inv; v.y *= inv; v.z *= inv; v.w *= inv;

    union { __nv_bfloat16 b[4]; uint2 u; } Ph, Pl;
    bsplit(v.x, Ph.b[0], Pl.b[0]); bsplit(v.y, Ph.b[1], Pl.b[1]);
    bsplit(v.z, Ph.b[2], Pl.b[2]); bsplit(v.w, Ph.b[3], Pl.b[3]);
    const size_t off = (size_t)blockIdx.x * NSP + threadIdx.x * 4;
    *(uint2*)(oh + off) = Ph.u;
    *(uint2*)(ol + off) = Pl.u;
}

__global__ void split_kernel(const float* __restrict__ s, __nv_bfloat16* __restrict__ h,
                             __nv_bfloat16* __restrict__ l, int n) {
    int i = (blockIdx.x * blockDim.x + threadIdx.x) * 4;
    if (i < n) {
        float4 v = *(const float4*)(s + i);
        union { __nv_bfloat16 b[4]; uint2 u; } Ph, Pl;
        bsplit(v.x, Ph.b[0], Pl.b[0]); bsplit(v.y, Ph.b[1], Pl.b[1]);
        bsplit(v.z, Ph.b[2], Pl.b[2]); bsplit(v.w, Ph.b[3], Pl.b[3]);
        *(uint2*)(h + i) = Ph.u;
        *(uint2*)(l + i) = Pl.u;
    }
}

// ---------------------------------------------------------------------------
extern "C" void kernel_launch(void* const* d_in, const int* in_sizes, int n_in,
                              void* d_out, int out_size) {
    const float* x    = (const float*)d_in[0];
    const float* nw   = (const float*)d_in[1];
    const float* nb   = (const float*)d_in[2];
    const float* qkvw = (const float*)d_in[3];
    const float* qkvb = (const float*)d_in[4];
    const float* pw   = (const float*)d_in[5];
    const float* pb   = (const float*)d_in[6];
    float* out = (float*)d_out;

    __nv_bfloat16 *hTh, *hTl, *qkh, *qkl, *vh, *vl, *ath, *atl, *oth, *otl,
                  *wqh, *wql, *wph, *wpl;
    float* attn;
    cudaGetSymbolAddress((void**)&hTh, g_hT_h);
    cudaGetSymbolAddress((void**)&hTl, g_hT_l);
    cudaGetSymbolAddress((void**)&qkh, g_qkT_h);
    cudaGetSymbolAddress((void**)&qkl, g_qkT_l);
    cudaGetSymbolAddress((void**)&vh, g_v_h);
    cudaGetSymbolAddress((void**)&vl, g_v_l);
    cudaGetSymbolAddress((void**)&attn, g_attn);
    cudaGetSymbolAddress((void**)&ath, g_attn_h);
    cudaGetSymbolAddress((void**)&atl, g_attn_l);
    cudaGetSymbolAddress((void**)&oth, g_oT_h);
    cudaGetSymbolAddress((void**)&otl, g_oT_l);
    cudaGetSymbolAddress((void**)&wqh, g_wqkv_h);
    cudaGetSymbolAddress((void**)&wql, g_wqkv_l);
    cudaGetSymbolAddress((void**)&wph, g_wp_h);
    cudaGetSymbolAddress((void**)&wpl, g_wp_l);

    cudaFuncSetAttribute(mma_gemm<0>, cudaFuncAttributeMaxDynamicSharedMemorySize, SMEM_BYTES);
    cudaFuncSetAttribute(mma_gemm<1>, cudaFuncAttributeMaxDynamicSharedMemorySize, SMEM_BYTES);
    cudaFuncSetAttribute(mma_gemm<2>, cudaFuncAttributeMaxDynamicSharedMemorySize, SMEM_BYTES);
    cudaFuncSetAttribute(mma_gemm<3>, cudaFuncAttributeMaxDynamicSharedMemorySize, SMEM_BYTES);
    cudaFuncSetAttribute(mma_gemm<4>, cudaFuncAttributeMaxDynamicSharedMemorySize, SMEM_BYTES);

    const long long sHT = (long long)NSP * CHN;
    const long long sQK = (long long)NSP * 1024;
    const long long sV  = (long long)CHN * NSP;
    const long long sAT = (long long)NSP * NSP;
    const float scale = 0.044194173824159216f;  // 512^-0.5

    split_kernel<<<768, 256>>>(qkvw, wqh, wql, 3 * CHN * CHN);
    split_kernel<<<256, 256>>>(pw, wph, wpl, CHN * CHN);

    // 1) GroupNorm -> hT hi/lo  [B, N, C]
    groupnorm_t<<<NB * 8, 256>>>(x, nw, nb, hTh, hTl);

    // 2) qkT[n, o] = sum_c hT[n,c] * Wqk[o,c] + qkv_b[o]
    mma_gemm<0><<<dim3(1024 / NT, NSP / MT, NB), 256, SMEM_BYTES>>>(
        hTh, hTl, CHN, sHT, wqh, wql, CHN, 0LL, CHN,
        nullptr, qkh, qkl, 1024, sQK, qkvb, nullptr, 0LL, 1.f);

    // 3) v[c, n] = sum_k Wv[c,k] * hT[n,k] + qkv_b[1024 + c]
    mma_gemm<1><<<dim3(NSP / NT, CHN / MT, NB), 256, SMEM_BYTES>>>(
        wqh + 1024 * CHN, wql + 1024 * CHN, CHN, 0LL, hTh, hTl, CHN, sHT, CHN,
        nullptr, vh, vl, NSP, sV, qkvb + 1024, nullptr, 0LL, 1.f);

    // 4) attn[i, j] = scale * sum_c qT[i,c] * kT[j,c]   (fp32 out)
    mma_gemm<2><<<dim3(NSP / NT, NSP / MT, NB), 256, SMEM_BYTES>>>(
        qkh, qkl, 1024, sQK, qkh + CHN, qkl + CHN, 1024, sQK, CHN,
        attn, nullptr, nullptr, NSP, sAT, nullptr, nullptr, 0LL, scale);

    // 5) softmax -> probs hi/lo
    softmax_split<<<NB * NSP, 256>>>(attn, ath, atl);

    // 6) oT[i, c] = sum_j attn[i,j] * v[c,j]
    mma_gemm<3><<<dim3(CHN / NT, NSP / MT, NB), 256, SMEM_BYTES>>>(
        ath, atl, NSP, sAT, vh, vl, NSP, sV, NSP,
        nullptr, oth, otl, CHN, sHT, nullptr, nullptr, 0LL, 1.f);

    // 7) out[o, n] = sum_c P[o,c] * oT[n,c] + pb[o] + x[b,o,n]
    mma_gemm<4><<<dim3(NSP / NT, CHN / MT, NB), 256, SMEM_BYTES>>>(
        wph, wpl, CHN, 0LL, oth, otl, CHN, sHT, CHN,
        out, nullptr, nullptr, NSP, sV, pb, x, sV, 1.f);
}